// round 1
// baseline (speedup 1.0000x reference)
#include <cuda_runtime.h>
#include <math.h>

#define BATCH   16384
#define D_IN    128
#define HID     16
#define N_INNER 255
#define N_LEAF  256
#define DEPTH   8

// ---------------- Kernel 1: fused GEMM (x @ W1) + relu + dot(W2) + sigmoid -> p --------
#define TB        128   // batch rows per block
#define NB        8     // nodes per block
#define THREADS1  512
#define XS_STRIDE 132   // pad: keeps float2 alignment (even) and breaks bank conflicts

#define FMA2(acc, xp, w) \
    asm("fma.rn.f32x2 %0, %1, %2, %0;" : "+l"(acc) : "l"(xp), "l"(w))

__global__ __launch_bounds__(THREADS1, 1)
void gemm_p_kernel(const float* __restrict__ x,  const float* __restrict__ W1,
                   const float* __restrict__ b1, const float* __restrict__ W2,
                   const float* __restrict__ b2, float* __restrict__ out)
{
    extern __shared__ float smem[];
    float* xs    = smem;                         // [k][row] padded, 128*132 floats
    float* ws    = xs + D_IN * XS_STRIDE;        // [n][k][h], 8*128*16 floats
    float* ptile = ws + NB * D_IN * HID;         // [row][n], 128*8 floats

    const int tid   = threadIdx.x;
    const int row0  = blockIdx.x * TB;
    const int node0 = blockIdx.y * NB;
    const int nb    = min(NB, N_INNER - node0);  // 8, or 7 for the last tile

    // Stage x tile, transposed: coalesced global reads, padded smem stores.
    for (int i = tid; i < TB * D_IN; i += THREADS1) {
        int r = i >> 7;        // / D_IN
        int k = i & (D_IN - 1);
        xs[k * XS_STRIDE + r] = x[(size_t)(row0 + r) * D_IN + k];
    }
    // Stage W1 slice: nodes node0..node0+nb-1 are contiguous in global.
    const float* w1g = W1 + (size_t)node0 * D_IN * HID;
    for (int i = tid; i < nb * D_IN * HID; i += THREADS1) {
        ws[i] = w1g[i];
    }
    __syncthreads();

    const int n  = tid >> 6;   // 0..7: node within block
    const int rg = tid & 63;   // 0..63: row-pair group

    // 16 HID accumulators per row as 8 packed f32x2 (lo=h even, hi=h odd), 2 rows.
    unsigned long long a0[8], a1[8];
    #pragma unroll
    for (int j = 0; j < 8; j++) { a0[j] = 0ull; a1[j] = 0ull; }

    if (n < nb) {
        const ulonglong2* wsn = (const ulonglong2*)(ws + n * (D_IN * HID));
        #pragma unroll 4
        for (int k = 0; k < D_IN; k++) {
            float2 xv = *(const float2*)(xs + k * XS_STRIDE + 2 * rg);
            unsigned long long xp0, xp1;
            asm("mov.b64 %0, {%1, %1};" : "=l"(xp0) : "f"(xv.x));
            asm("mov.b64 %0, {%1, %1};" : "=l"(xp1) : "f"(xv.y));
            // 16 weights for this (n,k): 4x LDS.128, broadcast across the warp
            ulonglong2 w0 = wsn[k * 4 + 0];
            ulonglong2 w1v = wsn[k * 4 + 1];
            ulonglong2 w2v = wsn[k * 4 + 2];
            ulonglong2 w3v = wsn[k * 4 + 3];
            FMA2(a0[0], xp0, w0.x);  FMA2(a1[0], xp1, w0.x);
            FMA2(a0[1], xp0, w0.y);  FMA2(a1[1], xp1, w0.y);
            FMA2(a0[2], xp0, w1v.x); FMA2(a1[2], xp1, w1v.x);
            FMA2(a0[3], xp0, w1v.y); FMA2(a1[3], xp1, w1v.y);
            FMA2(a0[4], xp0, w2v.x); FMA2(a1[4], xp1, w2v.x);
            FMA2(a0[5], xp0, w2v.y); FMA2(a1[5], xp1, w2v.y);
            FMA2(a0[6], xp0, w3v.x); FMA2(a1[6], xp1, w3v.x);
            FMA2(a0[7], xp0, w3v.y); FMA2(a1[7], xp1, w3v.y);
        }

        // Epilogue: +b1, relu, dot W2, +b2, sigmoid
        const int ng = node0 + n;
        float s0 = b2[ng];
        float s1 = s0;
        #pragma unroll
        for (int j = 0; j < 8; j++) {
            float u0, v0, u1, v1;
            asm("mov.b64 {%0, %1}, %2;" : "=f"(u0), "=f"(v0) : "l"(a0[j]));
            asm("mov.b64 {%0, %1}, %2;" : "=f"(u1), "=f"(v1) : "l"(a1[j]));
            float bb0 = b1[ng * HID + 2 * j];
            float bb1 = b1[ng * HID + 2 * j + 1];
            float wv0 = W2[ng * HID + 2 * j];
            float wv1 = W2[ng * HID + 2 * j + 1];
            s0 += fmaxf(u0 + bb0, 0.f) * wv0 + fmaxf(v0 + bb1, 0.f) * wv1;
            s1 += fmaxf(u1 + bb0, 0.f) * wv0 + fmaxf(v1 + bb1, 0.f) * wv1;
        }
        ptile[(2 * rg    ) * NB + n] = 1.f / (1.f + expf(-s0));
        ptile[(2 * rg + 1) * NB + n] = 1.f / (1.f + expf(-s1));
    }
    __syncthreads();

    // Write p tile: per-row 7-8 consecutive floats -> 1 sector/row instead of 8.
    float* outp = out + (size_t)BATCH * 257;  // p region base
    for (int i = tid; i < TB * nb; i += THREADS1) {
        int r = i / nb;
        int c = i - r * nb;
        outp[(size_t)(row0 + r) * N_INNER + node0 + c] = ptile[r * NB + c];
    }
}

// ---------------- Kernel 2: tree pass (warp per row) -----------------------------------
#define ROWS2    8
#define THREADS2 256

__global__ __launch_bounds__(THREADS2, 1)
void tree_kernel(const float* __restrict__ leaf, float* __restrict__ out)
{
    __shared__ float ps[ROWS2][256];
    __shared__ float rA[ROWS2][256];
    __shared__ float rB[ROWS2][256];
    __shared__ float leafs[256];

    const int tid  = threadIdx.x;
    const int wid  = tid >> 5;
    const int lane = tid & 31;
    const int row  = blockIdx.x * ROWS2 + wid;

    leafs[tid] = leaf[tid];

    const float* prow = out + (size_t)BATCH * 257 + (size_t)row * N_INNER;
    for (int i = lane; i < N_INNER; i += 32) ps[wid][i] = prow[i];
    if (lane == 0) rA[wid][0] = 1.f;
    __syncthreads();

    float* ra = rA[wid];
    float* rb = rB[wid];
    float* nr = out + (size_t)BATCH * 512 + (size_t)row * N_INNER;  // node_reach

    #pragma unroll
    for (int l = 0; l < DEPTH; l++) {
        const int sz = 1 << l;
        for (int j = lane; j < sz; j += 32) {
            float rv = ra[j];
            nr[sz - 1 + j] = rv;                 // node_reach for level l
            float pv = ps[wid][sz - 1 + j];
            rb[2 * j]     = rv * (1.f - pv);
            rb[2 * j + 1] = rv * pv;
        }
        __syncwarp();
        float* t = ra; ra = rb; rb = t;
    }

    // ra now holds path_probs (256)
    float* pp = out + (size_t)BATCH + (size_t)row * N_LEAF;
    float hsum = 0.f;
    for (int j = lane; j < N_LEAF; j += 32) {
        float v = ra[j];
        pp[j] = v;
        hsum += v * leafs[j];
    }
    #pragma unroll
    for (int o = 16; o; o >>= 1) hsum += __shfl_down_sync(0xffffffffu, hsum, o);
    if (lane == 0) out[row] = hsum;   // h
}

// ---------------- launch ----------------------------------------------------------------
extern "C" void kernel_launch(void* const* d_in, const int* in_sizes, int n_in,
                              void* d_out, int out_size)
{
    const float* x    = (const float*)d_in[0];
    const float* W1   = (const float*)d_in[1];
    const float* b1   = (const float*)d_in[2];
    const float* W2   = (const float*)d_in[3];
    const float* b2   = (const float*)d_in[4];
    const float* leaf = (const float*)d_in[5];
    float* out = (float*)d_out;

    const int smem1 = (D_IN * XS_STRIDE + NB * D_IN * HID + TB * NB) * (int)sizeof(float);
    cudaFuncSetAttribute(gemm_p_kernel, cudaFuncAttributeMaxDynamicSharedMemorySize, smem1);

    dim3 grid1(BATCH / TB, (N_INNER + NB - 1) / NB);
    gemm_p_kernel<<<grid1, THREADS1, smem1>>>(x, W1, b1, W2, b2, out);

    tree_kernel<<<BATCH / ROWS2, THREADS2>>>(leaf, out);
}

// round 4
// speedup vs baseline: 1.5705x; 1.5705x over previous
#include <cuda_runtime.h>
#include <cuda_bf16.h>
#include <math.h>
#include <stdint.h>

#define BATCH   16384
#define D_IN    128
#define HID     16
#define N_INNER 255
#define N_LEAF  256
#define DEPTH   8

#define NCOLS   4096   // padded (node,h) columns: 256*16
#define MT      128    // rows per CTA
#define NTILE   128    // cols per tile
#define NT      32     // col tiles
#define GT      512    // threads (16 warps, 4x4)

// ---------------- scratch (no allocs allowed) ----------------
__device__ __nv_bfloat16 g_xhi[BATCH * D_IN];
__device__ __nv_bfloat16 g_xlo[BATCH * D_IN];
__device__ __nv_bfloat16 g_whi[NCOLS * D_IN];
__device__ __nv_bfloat16 g_wlo[NCOLS * D_IN];

// ---------------- PTX helpers (base sm_103 target legal) ----------------
#define CP16(dst, src) \
    asm volatile("cp.async.cg.shared.global [%0], [%1], 16;" :: "r"(dst), "l"(src))
#define CP_COMMIT() asm volatile("cp.async.commit_group;" ::: "memory")
#define CP_WAIT0()  asm volatile("cp.async.wait_group 0;" ::: "memory")

#define LDSM4(R, addr) \
    asm volatile("ldmatrix.sync.aligned.m8n8.x4.shared.b16 {%0,%1,%2,%3}, [%4];" \
                 : "=r"((R)[0]), "=r"((R)[1]), "=r"((R)[2]), "=r"((R)[3]) : "r"(addr))

#define MMA16816(C, A, B0, B1) \
    asm volatile("mma.sync.aligned.m16n8k16.row.col.f32.bf16.bf16.f32 " \
                 "{%0,%1,%2,%3}, {%4,%5,%6,%7}, {%8,%9}, {%0,%1,%2,%3};" \
                 : "+f"((C)[0]), "+f"((C)[1]), "+f"((C)[2]), "+f"((C)[3]) \
                 : "r"((A)[0]), "r"((A)[1]), "r"((A)[2]), "r"((A)[3]), \
                   "r"(B0), "r"(B1))

// XOR swizzle for a 128x128-bf16 tile (256 B rows, 16B chunks):
// conflict-free for both cp.async stores and ldmatrix column reads.
__device__ __forceinline__ uint32_t sw_off(int r, int j) {
    return (uint32_t)(r * 256 + (((j & 8) | ((j ^ r) & 7)) << 4));
}

// ---------------- prep kernels ----------------
__global__ void cvt_x_kernel(const float* __restrict__ x) {
    int i = blockIdx.x * 256 + threadIdx.x;
    float v = x[i];
    __nv_bfloat16 h = __float2bfloat16(v);
    g_xhi[i] = h;
    g_xlo[i] = __float2bfloat16(v - __bfloat162float(h));
}

__global__ void cvt_w_kernel(const float* __restrict__ W1) {
    int i = blockIdx.x * 256 + threadIdx.x;   // over NCOLS*D_IN, layout [col][k]
    int col = i >> 7, k = i & 127;
    int n = col >> 4, h = col & 15;
    float v = (n < N_INNER) ? W1[(n * D_IN + k) * HID + h] : 0.f;
    __nv_bfloat16 hh = __float2bfloat16(v);
    g_whi[i] = hh;
    g_wlo[i] = __float2bfloat16(v - __bfloat162float(hh));
}

// ---------------- SMEM layout ----------------
// A: hi 32KB + lo 32KB @0 ; B: 2 bufs x (hi 32KB + lo 32KB) @65536 ; ptile @196608
#define SM_A   0
#define SM_B   65536
#define SM_PT  196608
#define SMEM_TOTAL (196608 + 4096)

__device__ __forceinline__ void load_tile(uint32_t dst, const __nv_bfloat16* src, int tid) {
    #pragma unroll
    for (int it = 0; it < 4; it++) {
        int c = tid + it * GT;           // 0..2047 chunks
        int r = c >> 4, j = c & 15;
        CP16(dst + sw_off(r, j), src + r * D_IN + j * 8);
    }
}

__global__ __launch_bounds__(GT, 1)
void gemm_mma_kernel(const float* __restrict__ b1, const float* __restrict__ W2,
                     const float* __restrict__ b2, float* __restrict__ out)
{
    extern __shared__ char smem[];
    uint32_t sb = (uint32_t)__cvta_generic_to_shared(smem);
    float* ptile = (float*)(smem + SM_PT);       // [128][8]

    const int tid    = threadIdx.x;
    const int lane   = tid & 31;
    const int wid    = tid >> 5;
    const int warp_m = wid & 3;                  // 4 x 32 rows
    const int warp_n = wid >> 2;                 // 4 x 32 cols
    const int row0   = blockIdx.x * MT;

    const float* b1f = b1;   // flat [255*16]
    const float* w2f = W2;   // flat [255*16]

    // Preload A (hi+lo) and B tile 0 (hi+lo)
    load_tile(sb + SM_A,           g_xhi + (size_t)row0 * D_IN, tid);
    load_tile(sb + SM_A + 32768u,  g_xlo + (size_t)row0 * D_IN, tid);
    load_tile(sb + SM_B,           g_whi, tid);
    load_tile(sb + SM_B + 32768u,  g_wlo, tid);
    CP_COMMIT();

    // Per-lane ldmatrix row/chunk components (constant across tiles)
    const int ra_base = warp_m * 32 + (lane & 7) + ((lane >> 3) & 1) * 8;  // + mf*16
    const int ja_add  = lane >> 4;
    const int rb_base = warp_n * 32 + (lane & 7) + ((lane >> 4) & 1) * 8;  // + bf*16
    const int jb_add  = (lane >> 3) & 1;

    float* outp = out + (size_t)BATCH * 257;     // p region

    for (int nt = 0; nt < NT; nt++) {
        const int s = nt & 1;

        CP_WAIT0();
        __syncthreads();   // B[s] ready; also fences previous ptile usage

        if (nt + 1 < NT) {
            uint32_t bb = sb + SM_B + (uint32_t)(1 - s) * 65536u;
            load_tile(bb,          g_whi + (size_t)(nt + 1) * NTILE * D_IN, tid);
            load_tile(bb + 32768u, g_wlo + (size_t)(nt + 1) * NTILE * D_IN, tid);
            CP_COMMIT();
        }

        float c[8][4];
        #pragma unroll
        for (int f = 0; f < 8; f++)
            #pragma unroll
            for (int e = 0; e < 4; e++) c[f][e] = 0.f;

        const uint32_t bbuf = sb + SM_B + (uint32_t)s * 65536u;

        #pragma unroll
        for (int term = 0; term < 3; term++) {
            const uint32_t abase = sb + SM_A + (term == 2 ? 32768u : 0u);
            const uint32_t bbase = bbuf + (term == 1 ? 32768u : 0u);
            #pragma unroll
            for (int ks = 0; ks < 8; ks++) {
                const int j0 = ks * 2;
                uint32_t a[2][4], b[2][4];
                #pragma unroll
                for (int mf = 0; mf < 2; mf++) {
                    int r = ra_base + mf * 16;
                    LDSM4(a[mf], abase + sw_off(r, j0 + ja_add));
                }
                #pragma unroll
                for (int bf = 0; bf < 2; bf++) {
                    int n = rb_base + bf * 16;
                    LDSM4(b[bf], bbase + sw_off(n, j0 + jb_add));
                }
                #pragma unroll
                for (int mf = 0; mf < 2; mf++)
                    #pragma unroll
                    for (int bf = 0; bf < 2; bf++)
                        #pragma unroll
                        for (int h = 0; h < 2; h++)
                            MMA16816(c[mf * 4 + bf * 2 + h], a[mf],
                                     b[bf][2 * h], b[bf][2 * h + 1]);
            }
        }

        // ---- epilogue: +b1, relu, dot W2, +b2, sigmoid -> ptile ----
        const int q = lane >> 2, g = lane & 3;
        #pragma unroll
        for (int m = 0; m < 2; m++) {
            #pragma unroll
            for (int nd = 0; nd < 2; nd++) {
                float s0 = 0.f, s1 = 0.f;
                #pragma unroll
                for (int h = 0; h < 2; h++) {
                    int f = m * 4 + nd * 2 + h;
                    int gcol = nt * 128 + warp_n * 32 + (nd * 2 + h) * 8 + 2 * g;
                    float bb0 = 0.f, ww0 = 0.f, bb1 = 0.f, ww1 = 0.f;
                    if (gcol < N_INNER * HID) {
                        bb0 = b1f[gcol];     ww0 = w2f[gcol];
                        bb1 = b1f[gcol + 1]; ww1 = w2f[gcol + 1];
                    }
                    s0 += fmaxf(c[f][0] + bb0, 0.f) * ww0 + fmaxf(c[f][1] + bb1, 0.f) * ww1;
                    s1 += fmaxf(c[f][2] + bb0, 0.f) * ww0 + fmaxf(c[f][3] + bb1, 0.f) * ww1;
                }
                s0 += __shfl_xor_sync(0xffffffffu, s0, 1);
                s0 += __shfl_xor_sync(0xffffffffu, s0, 2);
                s1 += __shfl_xor_sync(0xffffffffu, s1, 1);
                s1 += __shfl_xor_sync(0xffffffffu, s1, 2);
                if (g == nd) {
                    int nl = warp_n * 2 + nd;
                    int ng = nt * 8 + nl;
                    float b2v = (ng < N_INNER) ? b2[ng] : 0.f;
                    int r0 = warp_m * 32 + m * 16 + q;
                    ptile[r0 * 8 + nl]       = 1.f / (1.f + expf(-(s0 + b2v)));
                    ptile[(r0 + 8) * 8 + nl] = 1.f / (1.f + expf(-(s1 + b2v)));
                }
            }
        }
        __syncthreads();

        // coalesced p write: 8 consecutive floats per row
        #pragma unroll
        for (int i = tid; i < MT * 8; i += GT) {
            int r = i >> 3, cl = i & 7;
            int ng = nt * 8 + cl;
            if (ng < N_INNER)
                outp[(size_t)(row0 + r) * N_INNER + ng] = ptile[i];
        }
    }
}

// ---------------- Kernel 2: tree pass (warp per row) ----------------
#define ROWS2    8
#define THREADS2 256

__global__ __launch_bounds__(THREADS2, 1)
void tree_kernel(const float* __restrict__ leaf, float* __restrict__ out)
{
    __shared__ float ps[ROWS2][256];
    __shared__ float rA[ROWS2][256];
    __shared__ float rB[ROWS2][256];
    __shared__ float leafs[256];

    const int tid  = threadIdx.x;
    const int wid  = tid >> 5;
    const int lane = tid & 31;
    const int row  = blockIdx.x * ROWS2 + wid;

    leafs[tid] = leaf[tid];

    const float* prow = out + (size_t)BATCH * 257 + (size_t)row * N_INNER;
    for (int i = lane; i < N_INNER; i += 32) ps[wid][i] = prow[i];
    if (lane == 0) rA[wid][0] = 1.f;
    __syncthreads();

    float* ra = rA[wid];
    float* rb = rB[wid];
    float* nr = out + (size_t)BATCH * 512 + (size_t)row * N_INNER;  // node_reach

    #pragma unroll
    for (int l = 0; l < DEPTH; l++) {
        const int sz = 1 << l;
        for (int j = lane; j < sz; j += 32) {
            float rv = ra[j];
            nr[sz - 1 + j] = rv;
            float pv = ps[wid][sz - 1 + j];
            rb[2 * j]     = rv * (1.f - pv);
            rb[2 * j + 1] = rv * pv;
        }
        __syncwarp();
        float* t = ra; ra = rb; rb = t;
    }

    float* pp = out + (size_t)BATCH + (size_t)row * N_LEAF;
    float hsum = 0.f;
    for (int j = lane; j < N_LEAF; j += 32) {
        float v = ra[j];
        pp[j] = v;
        hsum += v * leafs[j];
    }
    #pragma unroll
    for (int o = 16; o; o >>= 1) hsum += __shfl_down_sync(0xffffffffu, hsum, o);
    if (lane == 0) out[row] = hsum;
}

// ---------------- launch ----------------
extern "C" void kernel_launch(void* const* d_in, const int* in_sizes, int n_in,
                              void* d_out, int out_size)
{
    const float* x    = (const float*)d_in[0];
    const float* W1   = (const float*)d_in[1];
    const float* b1   = (const float*)d_in[2];
    const float* W2   = (const float*)d_in[3];
    const float* b2   = (const float*)d_in[4];
    const float* leaf = (const float*)d_in[5];
    float* out = (float*)d_out;

    cvt_x_kernel<<<(BATCH * D_IN) / 256, 256>>>(x);
    cvt_w_kernel<<<(NCOLS * D_IN) / 256, 256>>>(W1);

    cudaFuncSetAttribute(gemm_mma_kernel, cudaFuncAttributeMaxDynamicSharedMemorySize, SMEM_TOTAL);
    gemm_mma_kernel<<<BATCH / MT, GT, SMEM_TOTAL>>>(b1, W2, b2, out);

    tree_kernel<<<BATCH / ROWS2, THREADS2>>>(leaf, out);
}

// round 5
// speedup vs baseline: 2.7929x; 1.7784x over previous
#include <cuda_runtime.h>
#include <cuda_fp16.h>
#include <math.h>
#include <stdint.h>

#define BATCH   16384
#define D_IN    128
#define HID     16
#define N_INNER 255
#define N_LEAF  256
#define DEPTH   8

#define NCOLS   4096   // padded (node,h) columns: 256*16
#define MT      128    // rows per CTA
#define NTILE   128    // cols per tile
#define NT      32     // col tiles
#define GT      512    // threads (16 warps, 4x4)

// ---------------- scratch (no allocs allowed) ----------------
__device__ __half g_xh[BATCH * D_IN];
__device__ __half g_wh[NCOLS * D_IN];
__device__ __half g_wl[NCOLS * D_IN];

// ---------------- PTX helpers (base sm_103 target legal) ----------------
#define CP16(dst, src) \
    asm volatile("cp.async.cg.shared.global [%0], [%1], 16;" :: "r"(dst), "l"(src))
#define CP_COMMIT() asm volatile("cp.async.commit_group;" ::: "memory")
#define CP_WAIT0()  asm volatile("cp.async.wait_group 0;" ::: "memory")

#define LDSM4(R, addr) \
    asm volatile("ldmatrix.sync.aligned.m8n8.x4.shared.b16 {%0,%1,%2,%3}, [%4];" \
                 : "=r"((R)[0]), "=r"((R)[1]), "=r"((R)[2]), "=r"((R)[3]) : "r"(addr))

#define MMA16816(C, A, B0, B1) \
    asm volatile("mma.sync.aligned.m16n8k16.row.col.f32.f16.f16.f32 " \
                 "{%0,%1,%2,%3}, {%4,%5,%6,%7}, {%8,%9}, {%0,%1,%2,%3};" \
                 : "+f"((C)[0]), "+f"((C)[1]), "+f"((C)[2]), "+f"((C)[3]) \
                 : "r"((A)[0]), "r"((A)[1]), "r"((A)[2]), "r"((A)[3]), \
                   "r"(B0), "r"(B1))

// XOR swizzle for a 128x128-f16 tile (256 B rows, 16B chunks):
// conflict-free for both cp.async stores and ldmatrix column reads.
__device__ __forceinline__ uint32_t sw_off(int r, int j) {
    return (uint32_t)(r * 256 + (((j & 8) | ((j ^ r) & 7)) << 4));
}

// ---------------- prep kernels ----------------
__global__ void cvt_x_kernel(const float* __restrict__ x) {
    int i = blockIdx.x * 256 + threadIdx.x;
    g_xh[i] = __float2half(x[i]);
}

// W1 [255][128 k][16 h] f32  ->  g_wh/g_wl [(n,h) col][k] f16, via smem transpose.
__global__ void cvt_w_kernel(const float* __restrict__ W1) {
    __shared__ float s[128 * 17 + 16];
    const int n   = blockIdx.x;          // 0..255
    const int tid = threadIdx.x;
    if (n < N_INNER) {
        for (int t = tid; t < 2048; t += 256) {
            int k = t >> 4, h = t & 15;
            s[k * 17 + h] = W1[n * 2048 + t];
        }
        __syncthreads();
        for (int t = tid; t < 2048; t += 256) {
            int h = t >> 7, k = t & 127;
            float v = s[k * 17 + h];
            __half hh = __float2half(v);
            int o = (n * HID + h) * D_IN + k;
            g_wh[o] = hh;
            g_wl[o] = __float2half(v - __half2float(hh));
        }
    } else {
        for (int t = tid; t < 2048; t += 256) {
            int o = n * HID * D_IN + t;
            g_wh[o] = __float2half(0.f);
            g_wl[o] = __float2half(0.f);
        }
    }
}

// ---------------- SMEM layout ----------------
// A(xh) 32KB @0 ; B 2 bufs x (wh 32KB + wl 32KB) @32768 ; bw table 32KB @163840 ; ptile @196608
#define SM_A   0
#define SM_B   32768
#define SM_BW  163840
#define SM_PT  196608
#define SMEM_TOTAL (196608 + 4096)

__device__ __forceinline__ void load_tile(uint32_t dst, const __half* src, int tid) {
    #pragma unroll
    for (int it = 0; it < 4; it++) {
        int c = tid + it * GT;           // 0..2047 chunks
        int r = c >> 4, j = c & 15;
        CP16(dst + sw_off(r, j), src + r * D_IN + j * 8);
    }
}

__global__ __launch_bounds__(GT, 1)
void gemm_mma_kernel(const float* __restrict__ b1, const float* __restrict__ W2,
                     const float* __restrict__ b2, float* __restrict__ out)
{
    extern __shared__ char smem[];
    uint32_t sb = (uint32_t)__cvta_generic_to_shared(smem);
    float*  ptile = (float*)(smem + SM_PT);      // [128][8]
    float2* bwS   = (float2*)(smem + SM_BW);     // [4096] {b1, W2}

    const int tid    = threadIdx.x;
    const int lane   = tid & 31;
    const int wid    = tid >> 5;
    const int warp_m = wid & 3;                  // 4 x 32 rows
    const int warp_n = wid >> 2;                 // 4 x 32 cols
    const int row0   = blockIdx.x * MT;

    // Preload A and B tile 0
    load_tile(sb + SM_A,           g_xh + (size_t)row0 * D_IN, tid);
    load_tile(sb + SM_B,           g_wh, tid);
    load_tile(sb + SM_B + 32768u,  g_wl, tid);
    CP_COMMIT();

    // One-time b1/W2 staging (cols 4080..4095 zero-padded)
    for (int i = tid; i < NCOLS; i += GT) {
        float bb = (i < N_INNER * HID) ? b1[i] : 0.f;
        float ww = (i < N_INNER * HID) ? W2[i] : 0.f;
        bwS[i] = make_float2(bb, ww);
    }

    const int ra_base = warp_m * 32 + (lane & 7) + ((lane >> 3) & 1) * 8;  // + mf*16
    const int ja_add  = lane >> 4;
    const int rb_base = warp_n * 32 + (lane & 7) + ((lane >> 4) & 1) * 8;  // + bf*16
    const int jb_add  = (lane >> 3) & 1;

    float* outp = out + (size_t)BATCH * 257;     // p region

    for (int nt = 0; nt < NT; nt++) {
        const int s = nt & 1;

        CP_WAIT0();
        __syncthreads();   // B[s] + bw ready; fences previous ptile readback

        if (nt + 1 < NT) {
            uint32_t bb = sb + SM_B + (uint32_t)(1 - s) * 65536u;
            load_tile(bb,          g_wh + (size_t)(nt + 1) * NTILE * D_IN, tid);
            load_tile(bb + 32768u, g_wl + (size_t)(nt + 1) * NTILE * D_IN, tid);
            CP_COMMIT();
        }

        float c[8][4];
        #pragma unroll
        for (int f = 0; f < 8; f++)
            #pragma unroll
            for (int e = 0; e < 4; e++) c[f][e] = 0.f;

        const uint32_t bhB = sb + SM_B + (uint32_t)s * 65536u;
        const uint32_t blB = bhB + 32768u;

        #pragma unroll
        for (int ks = 0; ks < 8; ks++) {
            const int j0 = ks * 2;
            uint32_t a[2][4], bh[2][4], bl[2][4];
            LDSM4(a[0],  sb + SM_A + sw_off(ra_base,      j0 + ja_add));
            LDSM4(a[1],  sb + SM_A + sw_off(ra_base + 16, j0 + ja_add));
            LDSM4(bh[0], bhB + sw_off(rb_base,      j0 + jb_add));
            LDSM4(bh[1], bhB + sw_off(rb_base + 16, j0 + jb_add));
            LDSM4(bl[0], blB + sw_off(rb_base,      j0 + jb_add));
            LDSM4(bl[1], blB + sw_off(rb_base + 16, j0 + jb_add));
            #pragma unroll
            for (int mf = 0; mf < 2; mf++)
                #pragma unroll
                for (int bf = 0; bf < 2; bf++)
                    #pragma unroll
                    for (int h = 0; h < 2; h++) {
                        float* cc = c[mf * 4 + bf * 2 + h];
                        MMA16816(cc, a[mf], bh[bf][2 * h], bh[bf][2 * h + 1]);
                        MMA16816(cc, a[mf], bl[bf][2 * h], bl[bf][2 * h + 1]);
                    }
        }

        // ---- epilogue: +b1, relu, dot W2, +b2, sigmoid -> ptile ----
        const int q = lane >> 2, g = lane & 3;
        #pragma unroll
        for (int m = 0; m < 2; m++) {
            #pragma unroll
            for (int nd = 0; nd < 2; nd++) {
                float s0 = 0.f, s1 = 0.f;
                #pragma unroll
                for (int h = 0; h < 2; h++) {
                    int f = m * 4 + nd * 2 + h;
                    int gcol = nt * 128 + warp_n * 32 + (nd * 2 + h) * 8 + 2 * g;
                    float2 bw0 = bwS[gcol];
                    float2 bw1 = bwS[gcol + 1];
                    s0 += fmaxf(c[f][0] + bw0.x, 0.f) * bw0.y + fmaxf(c[f][1] + bw1.x, 0.f) * bw1.y;
                    s1 += fmaxf(c[f][2] + bw0.x, 0.f) * bw0.y + fmaxf(c[f][3] + bw1.x, 0.f) * bw1.y;
                }
                s0 += __shfl_xor_sync(0xffffffffu, s0, 1);
                s0 += __shfl_xor_sync(0xffffffffu, s0, 2);
                s1 += __shfl_xor_sync(0xffffffffu, s1, 1);
                s1 += __shfl_xor_sync(0xffffffffu, s1, 2);
                if (g == nd) {
                    int nl = warp_n * 2 + nd;
                    int ng = nt * 8 + nl;
                    float b2v = (ng < N_INNER) ? b2[ng] : 0.f;
                    int r0 = warp_m * 32 + m * 16 + q;
                    ptile[r0 * 8 + nl]       = 1.f / (1.f + expf(-(s0 + b2v)));
                    ptile[(r0 + 8) * 8 + nl] = 1.f / (1.f + expf(-(s1 + b2v)));
                }
            }
        }
        __syncthreads();

        // coalesced p write: 8 consecutive floats per row
        #pragma unroll
        for (int i = tid; i < MT * 8; i += GT) {
            int r = i >> 3, cl = i & 7;
            int ng = nt * 8 + cl;
            if (ng < N_INNER)
                outp[(size_t)(row0 + r) * N_INNER + ng] = ptile[i];
        }
    }
}

// ---------------- Kernel 2: tree pass, shuffle-only (warp per row) ----------------
#define THREADS2 256

__global__ __launch_bounds__(THREADS2, 1)
void tree_kernel(const float* __restrict__ leaf, float* __restrict__ out)
{
    const int tid  = threadIdx.x;
    const int wid  = tid >> 5;
    const int lane = tid & 31;
    const int row  = blockIdx.x * 8 + wid;

    const float* prow = out + (size_t)BATCH * 257 + (size_t)row * N_INNER;
    float* nr = out + (size_t)BATCH * 512 + (size_t)row * N_INNER;
    float* pp = out + (size_t)BATCH + (size_t)row * N_LEAF;

    // Levels 0..4: one node per lane, expand via shfl
    float rv = (lane == 0) ? 1.f : 0.f;
    #pragma unroll
    for (int l = 0; l < 5; l++) {
        const int sz = 1 << l;
        float pv = 0.f;
        if (lane < sz) {
            nr[sz - 1 + lane] = rv;
            pv = prow[sz - 1 + lane];
        }
        float rp = __shfl_sync(0xffffffffu, rv, lane >> 1);
        float pq = __shfl_sync(0xffffffffu, pv, lane >> 1);
        rv = (lane & 1) ? rp * pq : rp * (1.f - pq);
    }

    // Level 5: 32 nodes, one per lane
    nr[31 + lane] = rv;
    float p5 = prow[31 + lane];
    float r6a = rv * (1.f - p5);
    float r6b = rv * p5;

    // Level 6: 2 nodes per lane (63 + 2*lane + {0,1})
    nr[63 + 2 * lane]     = r6a;
    nr[63 + 2 * lane + 1] = r6b;
    float p6a = prow[63 + 2 * lane];
    float p6b = prow[63 + 2 * lane + 1];
    float r7[4] = { r6a * (1.f - p6a), r6a * p6a, r6b * (1.f - p6b), r6b * p6b };

    // Level 7: 4 nodes per lane (127 + 4*lane + j)
    float p7[4];
    #pragma unroll
    for (int j = 0; j < 4; j++) {
        nr[127 + 4 * lane + j] = r7[j];
        p7[j] = prow[127 + 4 * lane + j];
    }

    // Leaves: 8 per lane
    float r8[8];
    #pragma unroll
    for (int j = 0; j < 4; j++) {
        r8[2 * j]     = r7[j] * (1.f - p7[j]);
        r8[2 * j + 1] = r7[j] * p7[j];
    }
    float4* pp4 = (float4*)(pp + 8 * lane);
    pp4[0] = make_float4(r8[0], r8[1], r8[2], r8[3]);
    pp4[1] = make_float4(r8[4], r8[5], r8[6], r8[7]);

    const float4* lf4 = (const float4*)(leaf + 8 * lane);
    float4 l0 = lf4[0], l1 = lf4[1];
    float hs = r8[0] * l0.x + r8[1] * l0.y + r8[2] * l0.z + r8[3] * l0.w
             + r8[4] * l1.x + r8[5] * l1.y + r8[6] * l1.z + r8[7] * l1.w;
    #pragma unroll
    for (int o = 16; o; o >>= 1) hs += __shfl_down_sync(0xffffffffu, hs, o);
    if (lane == 0) out[row] = hs;
}

// ---------------- launch ----------------
extern "C" void kernel_launch(void* const* d_in, const int* in_sizes, int n_in,
                              void* d_out, int out_size)
{
    const float* x    = (const float*)d_in[0];
    const float* W1   = (const float*)d_in[1];
    const float* b1   = (const float*)d_in[2];
    const float* W2   = (const float*)d_in[3];
    const float* b2   = (const float*)d_in[4];
    const float* leaf = (const float*)d_in[5];
    float* out = (float*)d_out;

    cvt_x_kernel<<<(BATCH * D_IN) / 256, 256>>>(x);
    cvt_w_kernel<<<256, 256>>>(W1);

    cudaFuncSetAttribute(gemm_mma_kernel, cudaFuncAttributeMaxDynamicSharedMemorySize, SMEM_TOTAL);
    gemm_mma_kernel<<<BATCH / MT, GT, SMEM_TOTAL>>>(b1, W2, b2, out);

    tree_kernel<<<BATCH / 8, THREADS2>>>(leaf, out);
}

// round 7
// speedup vs baseline: 3.5737x; 1.2796x over previous
#include <cuda_runtime.h>
#include <cuda_fp16.h>
#include <math.h>
#include <stdint.h>

#define BATCH   16384
#define D_IN    128
#define HID     16
#define N_INNER 255
#define N_LEAF  256
#define DEPTH   8

#define NCOLS   4096   // padded (node,h) columns: 256*16
#define MT      128    // rows per CTA
#define NTILE   128    // cols per tile
#define NT      32     // col tiles
#define GT      512    // threads (16 warps, 4x4)

// ---------------- scratch (no allocs allowed) ----------------
__device__ __half g_xh[BATCH * D_IN];
__device__ __half g_wh[NCOLS * D_IN];

// ---------------- PTX helpers (base sm_103 target legal) ----------------
#define CP16(dst, src) \
    asm volatile("cp.async.cg.shared.global [%0], [%1], 16;" :: "r"(dst), "l"(src))
#define CP_COMMIT() asm volatile("cp.async.commit_group;" ::: "memory")
#define CP_WAIT0()  asm volatile("cp.async.wait_group 0;" ::: "memory")

#define LDSM4(R, addr) \
    asm volatile("ldmatrix.sync.aligned.m8n8.x4.shared.b16 {%0,%1,%2,%3}, [%4];" \
                 : "=r"((R)[0]), "=r"((R)[1]), "=r"((R)[2]), "=r"((R)[3]) : "r"(addr))

#define MMA16816(C, A, B0, B1) \
    asm volatile("mma.sync.aligned.m16n8k16.row.col.f32.f16.f16.f32 " \
                 "{%0,%1,%2,%3}, {%4,%5,%6,%7}, {%8,%9}, {%0,%1,%2,%3};" \
                 : "+f"((C)[0]), "+f"((C)[1]), "+f"((C)[2]), "+f"((C)[3]) \
                 : "r"((A)[0]), "r"((A)[1]), "r"((A)[2]), "r"((A)[3]), \
                   "r"(B0), "r"(B1))

// XOR swizzle for a 128x128-f16 tile (256 B rows, 16B chunks):
// conflict-free for both cp.async stores and ldmatrix column reads.
__device__ __forceinline__ uint32_t sw_off(int r, int j) {
    return (uint32_t)(r * 256 + (((j & 8) | ((j ^ r) & 7)) << 4));
}

// ---------------- prep kernels ----------------
__global__ void cvt_x_kernel(const float* __restrict__ x) {
    int i = blockIdx.x * 256 + threadIdx.x;
    g_xh[i] = __float2half(x[i]);
}

// W1 [255][128 k][16 h] f32  ->  g_wh [(n,h) col][k] f16, via smem transpose.
__global__ void cvt_w_kernel(const float* __restrict__ W1) {
    __shared__ float s[128 * 17 + 16];
    const int n   = blockIdx.x;          // 0..255
    const int tid = threadIdx.x;
    if (n < N_INNER) {
        for (int t = tid; t < 2048; t += 256) {
            int k = t >> 4, h = t & 15;
            s[k * 17 + h] = W1[n * 2048 + t];
        }
        __syncthreads();
        for (int t = tid; t < 2048; t += 256) {
            int h = t >> 7, k = t & 127;
            g_wh[(n * HID + h) * D_IN + k] = __float2half(s[k * 17 + h]);
        }
    } else {
        for (int t = tid; t < 2048; t += 256)
            g_wh[n * HID * D_IN + t] = __float2half(0.f);
    }
}

// ---------------- SMEM layout ----------------
// A(xh) 32KB @0 ; B 2 bufs x 32KB @32768 ; bw table 32KB @98304 ; ptile 4KB @131072
#define SM_A   0
#define SM_B   32768
#define SM_BW  98304
#define SM_PT  131072
#define SMEM_TOTAL (131072 + 4096)

__device__ __forceinline__ void load_tile(uint32_t dst, const __half* src, int tid) {
    #pragma unroll
    for (int it = 0; it < 4; it++) {
        int c = tid + it * GT;           // 0..2047 chunks
        int r = c >> 4, j = c & 15;
        CP16(dst + sw_off(r, j), src + r * D_IN + j * 8);
    }
}

__global__ __launch_bounds__(GT, 1)
void gemm_mma_kernel(const float* __restrict__ b1, const float* __restrict__ W2,
                     const float* __restrict__ b2, float* __restrict__ out)
{
    extern __shared__ char smem[];
    uint32_t sb = (uint32_t)__cvta_generic_to_shared(smem);
    float*  ptile = (float*)(smem + SM_PT);      // [128][8]
    float2* bwS   = (float2*)(smem + SM_BW);     // [4096] {b1, W2}

    const int tid    = threadIdx.x;
    const int lane   = tid & 31;
    const int wid    = tid >> 5;
    const int warp_m = wid & 3;                  // 4 x 32 rows
    const int warp_n = wid >> 2;                 // 4 x 32 cols
    const int row0   = blockIdx.x * MT;

    // Preload A and B tile 0
    load_tile(sb + SM_A, g_xh + (size_t)row0 * D_IN, tid);
    load_tile(sb + SM_B, g_wh, tid);
    CP_COMMIT();

    // One-time b1/W2 staging (cols 4080..4095 zero-padded)
    for (int i = tid; i < NCOLS; i += GT) {
        float bb = (i < N_INNER * HID) ? b1[i] : 0.f;
        float ww = (i < N_INNER * HID) ? W2[i] : 0.f;
        bwS[i] = make_float2(bb, ww);
    }

    const int ra_base = warp_m * 32 + (lane & 7) + ((lane >> 3) & 1) * 8;  // + mf*16
    const int ja_add  = lane >> 4;
    const int rb_base = warp_n * 32 + (lane & 7) + ((lane >> 4) & 1) * 8;  // + bf*16
    const int jb_add  = (lane >> 3) & 1;

    float* outp = out + (size_t)BATCH * 257;     // p region

    for (int nt = 0; nt < NT; nt++) {
        const int s = nt & 1;

        CP_WAIT0();
        __syncthreads();   // B[s] + bw ready; fences previous ptile readback

        if (nt + 1 < NT) {
            load_tile(sb + SM_B + (uint32_t)(1 - s) * 32768u,
                      g_wh + (size_t)(nt + 1) * NTILE * D_IN, tid);
            CP_COMMIT();
        }

        float c[8][4];
        #pragma unroll
        for (int f = 0; f < 8; f++)
            #pragma unroll
            for (int e = 0; e < 4; e++) c[f][e] = 0.f;

        const uint32_t bB = sb + SM_B + (uint32_t)s * 32768u;

        #pragma unroll
        for (int ks = 0; ks < 8; ks++) {
            const int j0 = ks * 2;
            uint32_t a[2][4], bh[2][4];
            LDSM4(a[0],  sb + SM_A + sw_off(ra_base,      j0 + ja_add));
            LDSM4(a[1],  sb + SM_A + sw_off(ra_base + 16, j0 + ja_add));
            LDSM4(bh[0], bB + sw_off(rb_base,      j0 + jb_add));
            LDSM4(bh[1], bB + sw_off(rb_base + 16, j0 + jb_add));
            #pragma unroll
            for (int mf = 0; mf < 2; mf++)
                #pragma unroll
                for (int bf = 0; bf < 2; bf++)
                    #pragma unroll
                    for (int h = 0; h < 2; h++)
                        MMA16816(c[mf * 4 + bf * 2 + h], a[mf],
                                 bh[bf][2 * h], bh[bf][2 * h + 1]);
        }

        // ---- epilogue: +b1, relu, dot W2, +b2, sigmoid -> ptile ----
        const int q = lane >> 2, g = lane & 3;
        #pragma unroll
        for (int m = 0; m < 2; m++) {
            #pragma unroll
            for (int nd = 0; nd < 2; nd++) {
                float s0 = 0.f, s1 = 0.f;
                #pragma unroll
                for (int h = 0; h < 2; h++) {
                    int f = m * 4 + nd * 2 + h;
                    int gcol = nt * 128 + warp_n * 32 + (nd * 2 + h) * 8 + 2 * g;
                    float2 bw0 = bwS[gcol];
                    float2 bw1 = bwS[gcol + 1];
                    s0 += fmaxf(c[f][0] + bw0.x, 0.f) * bw0.y + fmaxf(c[f][1] + bw1.x, 0.f) * bw1.y;
                    s1 += fmaxf(c[f][2] + bw0.x, 0.f) * bw0.y + fmaxf(c[f][3] + bw1.x, 0.f) * bw1.y;
                }
                s0 += __shfl_xor_sync(0xffffffffu, s0, 1);
                s0 += __shfl_xor_sync(0xffffffffu, s0, 2);
                s1 += __shfl_xor_sync(0xffffffffu, s1, 1);
                s1 += __shfl_xor_sync(0xffffffffu, s1, 2);
                if (g == nd) {
                    int nl = warp_n * 2 + nd;
                    int ng = nt * 8 + nl;
                    float b2v = (ng < N_INNER) ? b2[ng] : 0.f;
                    int r0 = warp_m * 32 + m * 16 + q;
                    ptile[r0 * 8 + nl]       = 1.f / (1.f + expf(-(s0 + b2v)));
                    ptile[(r0 + 8) * 8 + nl] = 1.f / (1.f + expf(-(s1 + b2v)));
                }
            }
        }
        __syncthreads();

        // coalesced p write: 8 consecutive floats per row
        #pragma unroll
        for (int i = tid; i < MT * 8; i += GT) {
            int r = i >> 3, cl = i & 7;
            int ng = nt * 8 + cl;
            if (ng < N_INNER)
                outp[(size_t)(row0 + r) * N_INNER + ng] = ptile[i];
        }
    }
}

// ---------------- Kernel 2: tree pass, shuffle-only, loads hoisted ----------------
#define THREADS2 256

__global__ __launch_bounds__(THREADS2, 1)
void tree_kernel(const float* __restrict__ leaf, float* __restrict__ out)
{
    const int tid  = threadIdx.x;
    const int wid  = tid >> 5;
    const int lane = tid & 31;
    const int row  = blockIdx.x * 8 + wid;

    const float* prow = out + (size_t)BATCH * 257 + (size_t)row * N_INNER;
    float* nr = out + (size_t)BATCH * 512 + (size_t)row * N_INNER;
    float* pp = out + (size_t)BATCH + (size_t)row * N_LEAF;

    // ---- hoist ALL p loads (address-independent; MLP=12) ----
    float pl[5];
    #pragma unroll
    for (int l = 0; l < 5; l++) {
        const int sz = 1 << l;
        pl[l] = (lane < sz) ? __ldg(prow + sz - 1 + lane) : 0.f;
    }
    float p5  = __ldg(prow + 31 + lane);
    float p6a = __ldg(prow + 63 + 2 * lane);
    float p6b = __ldg(prow + 63 + 2 * lane + 1);
    float p7[4];
    #pragma unroll
    for (int j = 0; j < 4; j++) p7[j] = __ldg(prow + 127 + 4 * lane + j);

    const float4* lf4 = (const float4*)(leaf + 8 * lane);
    float4 l0 = lf4[0], l1 = lf4[1];

    // ---- expansion chain ----
    float rv = (lane == 0) ? 1.f : 0.f;
    #pragma unroll
    for (int l = 0; l < 5; l++) {
        const int sz = 1 << l;
        if (lane < sz) nr[sz - 1 + lane] = rv;
        float rp = __shfl_sync(0xffffffffu, rv, lane >> 1);
        float pq = __shfl_sync(0xffffffffu, pl[l], lane >> 1);
        rv = (lane & 1) ? rp * pq : rp * (1.f - pq);
    }

    nr[31 + lane] = rv;
    float r6a = rv * (1.f - p5);
    float r6b = rv * p5;

    nr[63 + 2 * lane]     = r6a;
    nr[63 + 2 * lane + 1] = r6b;
    float r7[4] = { r6a * (1.f - p6a), r6a * p6a, r6b * (1.f - p6b), r6b * p6b };

    #pragma unroll
    for (int j = 0; j < 4; j++) nr[127 + 4 * lane + j] = r7[j];

    float r8[8];
    #pragma unroll
    for (int j = 0; j < 4; j++) {
        r8[2 * j]     = r7[j] * (1.f - p7[j]);
        r8[2 * j + 1] = r7[j] * p7[j];
    }
    float4* pp4 = (float4*)(pp + 8 * lane);
    pp4[0] = make_float4(r8[0], r8[1], r8[2], r8[3]);
    pp4[1] = make_float4(r8[4], r8[5], r8[6], r8[7]);

    float hs = r8[0] * l0.x + r8[1] * l0.y + r8[2] * l0.z + r8[3] * l0.w
             + r8[4] * l1.x + r8[5] * l1.y + r8[6] * l1.z + r8[7] * l1.w;
    #pragma unroll
    for (int o = 16; o; o >>= 1) hs += __shfl_down_sync(0xffffffffu, hs, o);
    if (lane == 0) out[row] = hs;
}

// ---------------- launch ----------------
extern "C" void kernel_launch(void* const* d_in, const int* in_sizes, int n_in,
                              void* d_out, int out_size)
{
    const float* x    = (const float*)d_in[0];
    const float* W1   = (const float*)d_in[1];
    const float* b1   = (const float*)d_in[2];
    const float* W2   = (const float*)d_in[3];
    const float* b2   = (const float*)d_in[4];
    const float* leaf = (const float*)d_in[5];
    float* out = (float*)d_out;

    cvt_x_kernel<<<(BATCH * D_IN) / 256, 256>>>(x);
    cvt_w_kernel<<<256, 256>>>(W1);

    cudaFuncSetAttribute(gemm_mma_kernel, cudaFuncAttributeMaxDynamicSharedMemorySize, SMEM_TOTAL);
    gemm_mma_kernel<<<BATCH / MT, GT, SMEM_TOTAL>>>(b1, W2, b2, out);

    tree_kernel<<<BATCH / 8, THREADS2>>>(leaf, out);
}